// round 10
// baseline (speedup 1.0000x reference)
#include <cuda_runtime.h>
#include <cuda_bf16.h>
#include <math.h>
#include <float.h>
#include <stdint.h>

// Problem constants
#define NPTS   131072          // 32 * 64 * 64 points
#define DDIM   64
#define KCODES 1024
#define HWSZ   4096
#define QOFF   ((size_t)NPTS)
#define QSZ    ((size_t)32*64*4096)
#define POFF   (QOFF + QSZ)

#define TAU    1e-2f           // int8-path gap gate (>6 sigma of quant noise)

#define PITCH   80             // int8 rows: 64B data + pad -> conflict-free ldmatrix
#define DTILE   (128 * PITCH)  // 10240 B: one digit tile (128 rows x 64 int8)
#define BUFSZ   (2 * DTILE)    // 20480 B: one buffer (hi + lo digits)
// smem layout (A digit tiles overlaid with B buffer 0)
#define SM_ESQ   0             // 1024 f32 = 4096
#define SM_FIDX  4096
#define SM_CNT   4608
#define SM_LST   4624
#define SM_XV    5152          // 8 warps x 64 f32
#define SM_BUF0  7200
#define SM_BUF1  (SM_BUF0 + BUFSZ)
#define SM_TOTAL (SM_BUF1 + BUFSZ)   // 48160 B

// ---- scratch (no cudaMalloc) ----
__device__ int    g_counts[KCODES];
__device__ float  g_esq[KCODES];
__device__ __align__(16) int8_t g_eh[KCODES * DDIM];
__device__ __align__(16) int8_t g_el[KCODES * DDIM];

// ---- PTX helpers (baseline ISA, sm_80-compatible) ----
__device__ __forceinline__ uint32_t smem_u32(const void* p) {
    uint32_t a;
    asm("{ .reg .u64 t; cvta.to.shared.u64 t, %1; cvt.u32.u64 %0, t; }"
        : "=r"(a) : "l"(p));
    return a;
}
#define CP_ASYNC16(dst, src) \
    asm volatile("cp.async.cg.shared.global [%0], [%1], 16;" \
                 :: "r"(dst), "l"(src) : "memory")
#define CP_COMMIT() asm volatile("cp.async.commit_group;" ::: "memory")
#define CP_WAIT1()  asm volatile("cp.async.wait_group 1;" ::: "memory")
#define CP_WAIT0()  asm volatile("cp.async.wait_group 0;" ::: "memory")

#define LDSM_X4(r, addr)                                                      \
    asm volatile("ldmatrix.sync.aligned.m8n8.x4.shared.b16 {%0,%1,%2,%3}, [%4];" \
                 : "=r"((r)[0]), "=r"((r)[1]), "=r"((r)[2]), "=r"((r)[3])     \
                 : "r"(addr))

#define IMMA(c, a, b0, b1)                                                    \
    asm volatile("mma.sync.aligned.m16n8k32.row.col.s32.s8.s8.s32 "           \
                 "{%0,%1,%2,%3}, {%4,%5,%6,%7}, {%8,%9}, {%0,%1,%2,%3};"      \
                 : "+r"((c)[0]), "+r"((c)[1]), "+r"((c)[2]), "+r"((c)[3])     \
                 : "r"((a)[0]), "r"((a)[1]), "r"((a)[2]), "r"((a)[3]),        \
                   "r"(b0), "r"(b1))

// best + second-best distance (index only for best)
__device__ __forceinline__ void upd2(float& bd, int& bi, float& sd,
                                     float d, int idx) {
    if (d < bd)      { sd = bd; bd = d; bi = idx; }
    else if (d < sd) { sd = d; }
}
__device__ __forceinline__ void merge2(float& bd, int& bi, float& sd,
                                       float obd, int obi, float osd) {
    if (obd < bd || (obd == bd && obi < bi)) {
        sd = fminf(bd, osd); bd = obd; bi = obi;
    } else {
        sd = fminf(sd, obd);
    }
}

__device__ __forceinline__ uint32_t pack4(int b0, int b1, int b2, int b3) {
    return (uint32_t)(b0 & 255) | ((uint32_t)(b1 & 255) << 8) |
           ((uint32_t)(b2 & 255) << 16) | ((uint32_t)(b3 & 255) << 24);
}

// ---------------------------------------------------------------------------
// esq: VERBATIM Round-1 arithmetic (matches reference decisions) + zero counts
// ---------------------------------------------------------------------------
__global__ void vq_prep(const float* __restrict__ emb) {
    int k = blockIdx.x * blockDim.x + threadIdx.x;
    if (k < KCODES) {
        const float4* row = (const float4*)(emb + (size_t)k * DDIM);
        float s = 0.f;
#pragma unroll
        for (int i = 0; i < DDIM / 4; i++) {
            float4 v = row[i];
            s += v.x * v.x + v.y * v.y + v.z * v.z + v.w * v.w;
        }
        g_esq[k]    = s;
        g_counts[k] = 0;
    }
}

// e digits: ef = rint(e*4096); hi = (ef+128)>>8; lo = ef - hi*256.
// 16384 threads, each converts 4 consecutive dims (float4 -> char4 x2).
__global__ void vq_digits(const float* __restrict__ emb) {
    int idx = blockIdx.x * blockDim.x + threadIdx.x;   // 0..16383
    int k = idx >> 4, g = idx & 15;
    float4 v = *(const float4*)(emb + (size_t)k * DDIM + g * 4);
    int f0 = __float2int_rn(v.x * 4096.0f);
    int f1 = __float2int_rn(v.y * 4096.0f);
    int f2 = __float2int_rn(v.z * 4096.0f);
    int f3 = __float2int_rn(v.w * 4096.0f);
    int h0 = (f0 + 128) >> 8, h1 = (f1 + 128) >> 8;
    int h2 = (f2 + 128) >> 8, h3 = (f3 + 128) >> 8;
    *(uint32_t*)(g_eh + (size_t)k * DDIM + g * 4) = pack4(h0, h1, h2, h3);
    *(uint32_t*)(g_el + (size_t)k * DDIM + g * 4) =
        pack4(f0 - (h0 << 8), f1 - (h1 << 8), f2 - (h2 << 8), f3 - (h3 << 8));
}

// ---------------------------------------------------------------------------
// Main: 256 threads (8 warps), 128 points/CTA, 1024 CTAs, 2 CTAs/SM.
// int8 digit MMA ranking (exact int32 accum) + gap-gated R1-exact rescan.
// ---------------------------------------------------------------------------
__global__ __launch_bounds__(256, 2)
void vq_main(const float* __restrict__ in, const float* __restrict__ emb,
             float* __restrict__ out) {
    extern __shared__ char smem[];
    float* esq_s = (float*)(smem + SM_ESQ);
    int*   fidx  = (int*)(smem + SM_FIDX);
    int*   pcnt  = (int*)(smem + SM_CNT);
    int*   lst   = (int*)(smem + SM_LST);
    const uint32_t sbase = smem_u32(smem);
    const int t    = threadIdx.x;
    const int lane = t & 31;
    const int w    = t >> 5;
    const int m0   = w * 16;
    const int base = blockIdx.x * 128;
    const int b    = base >> 12;
    const int tg   = lane & 3;

    // ---- B loader: 2 digits x 128 codes x 4 x 16B chunks = 4 cp per thread
    auto issue_B = [&](int tt, int buf) {
        uint32_t bb = sbase + (buf ? SM_BUF1 : SM_BUF0);
#pragma unroll
        for (int i = 0; i < 4; i++) {
            int c   = t + i * 256;           // 0..1023
            int dig = c >> 9;
            int r   = c & 511;
            int row = r >> 2, ch = r & 3;
            uint32_t dst = bb + dig * DTILE + row * PITCH + ch * 16;
            const int8_t* srcp = dig ? g_el : g_eh;
            const char* src = (const char*)srcp +
                              (size_t)(tt * 128 + row) * DDIM + ch * 16;
            CP_ASYNC16(dst, src);
        }
        CP_COMMIT();
    };

    if (t == 0) *pcnt = 0;
#pragma unroll
    for (int i = 0; i < KCODES / 256; i++)
        esq_s[t + i * 256] = g_esq[t + i * 256];

    // ---- A build into BUF0: quantize (-2x)*2048 = x*(-4096), digit split ----
    if (t < 128) {
        const float* xp = in + (size_t)b * DDIM * HWSZ + ((base + t) & (HWSZ - 1));
        char* rh = smem + SM_BUF0 + 0 * DTILE + t * PITCH;
        char* rl = smem + SM_BUF0 + 1 * DTILE + t * PITCH;
#pragma unroll
        for (int c = 0; c < 4; c++) {        // 16B chunk = dims 16c..16c+15
            uint32_t ph[4], pl[4];
#pragma unroll
            for (int i = 0; i < 4; i++) {
                int d = c * 16 + i * 4;
                int f0 = __float2int_rn(xp[(size_t)(d + 0) * HWSZ] * -4096.0f);
                int f1 = __float2int_rn(xp[(size_t)(d + 1) * HWSZ] * -4096.0f);
                int f2 = __float2int_rn(xp[(size_t)(d + 2) * HWSZ] * -4096.0f);
                int f3 = __float2int_rn(xp[(size_t)(d + 3) * HWSZ] * -4096.0f);
                int h0 = (f0 + 128) >> 8, h1 = (f1 + 128) >> 8;
                int h2 = (f2 + 128) >> 8, h3 = (f3 + 128) >> 8;
                ph[i] = pack4(h0, h1, h2, h3);
                pl[i] = pack4(f0 - (h0 << 8), f1 - (h1 << 8),
                              f2 - (h2 << 8), f3 - (h3 << 8));
            }
            *(uint4*)(rh + c * 16) = make_uint4(ph[0], ph[1], ph[2], ph[3]);
            *(uint4*)(rl + c * 16) = make_uint4(pl[0], pl[1], pl[2], pl[3]);
        }
    }
    __syncthreads();

    // ---- A fragments: af[digit][kstep][4] via ldmatrix ----
    uint32_t af[2][2][4];
#pragma unroll
    for (int dig = 0; dig < 2; dig++)
#pragma unroll
        for (int ks = 0; ks < 2; ks++) {
            uint32_t addr = sbase + SM_BUF0 + dig * DTILE +
                            (m0 + (lane & 15)) * PITCH + ks * 32 +
                            (lane >> 4) * 16;
            LDSM_X4(af[dig][ks], addr);
        }
    __syncthreads();                         // LDSM done before BUF0 overwrite

    issue_B(0, 0);
    issue_B(1, 1);

    float bd0 = FLT_MAX, sd0 = FLT_MAX, bd1 = FLT_MAX, sd1 = FLT_MAX;
    int   bi0 = 0, bi1 = 0;

    const float SHH = 0.0078125f;            // 2^16 / 2^23
    const float SHL = 3.0517578125e-05f;     // 2^8  / 2^23
    const float SLL = 1.1920928955078125e-07f; // 1 / 2^23

    for (int tt = 0; tt < 8; tt++) {
        if (tt < 7) { CP_WAIT1(); } else { CP_WAIT0(); }
        __syncthreads();
        const uint32_t bbase = sbase + ((tt & 1) ? SM_BUF1 : SM_BUF0);

#pragma unroll 2
        for (int j = 0; j < 16; j++) {
            // B fragments: bh/bl, 4 regs = 4 k-chunks of 16B
            uint32_t bh[4], bl[4];
            {
                uint32_t ra = bbase + (j * 8 + (lane & 7)) * PITCH +
                              (lane >> 3) * 16;
                LDSM_X4(bh, ra);
                LDSM_X4(bl, ra + DTILE);
            }

            int chh[4] = {0, 0, 0, 0}, chl[4] = {0, 0, 0, 0};
            int clh[4] = {0, 0, 0, 0}, cll[4] = {0, 0, 0, 0};
#pragma unroll
            for (int ks = 0; ks < 2; ks++) {
                IMMA(chh, af[0][ks], bh[2 * ks], bh[2 * ks + 1]);
                IMMA(chl, af[0][ks], bl[2 * ks], bl[2 * ks + 1]);
                IMMA(clh, af[1][ks], bh[2 * ks], bh[2 * ks + 1]);
                IMMA(cll, af[1][ks], bl[2 * ks], bl[2 * ks + 1]);
            }

            const int cb = tt * 128 + j * 8 + 2 * tg;
            const float e0 = esq_s[cb], e1 = esq_s[cb + 1];
#pragma unroll
            for (int p = 0; p < 4; p++) {
                float v = fmaf((float)chh[p], SHH,
                          fmaf((float)(chl[p] + clh[p]), SHL,
                               (float)cll[p] * SLL));
                float d = ((p & 1) ? e1 : e0) + v;
                if (p < 2) upd2(bd0, bi0, sd0, d, cb + (p & 1));
                else       upd2(bd1, bi1, sd1, d, cb + (p & 1));
            }
        }

        __syncthreads();                     // everyone done reading buf
        if (tt + 2 < 8) issue_B(tt + 2, tt & 1);
    }

    // ---- merge top-2 across the 4 lanes sharing each row ----
#pragma unroll
    for (int off = 1; off <= 2; off <<= 1) {
        float obd = __shfl_xor_sync(0xffffffffu, bd0, off);
        int   obi = __shfl_xor_sync(0xffffffffu, bi0, off);
        float osd = __shfl_xor_sync(0xffffffffu, sd0, off);
        merge2(bd0, bi0, sd0, obd, obi, osd);
        obd = __shfl_xor_sync(0xffffffffu, bd1, off);
        obi = __shfl_xor_sync(0xffffffffu, bi1, off);
        osd = __shfl_xor_sync(0xffffffffu, sd1, off);
        merge2(bd1, bi1, sd1, obd, obi, osd);
    }
    if (tg == 0) {
        int g  = lane >> 2;
        int r0 = m0 + g, r1 = m0 + g + 8;
        fidx[r0] = bi0;
        fidx[r1] = bi1;
        if (sd0 - bd0 <= TAU) lst[atomicAdd(pcnt, 1)] = r0;
        if (sd1 - bd1 <= TAU) lst[atomicAdd(pcnt, 1)] = r1;
    }
    __syncthreads();

    // ---- near-tie rescan: EXACT Round-1 arithmetic, all 1024 codes ----
    {
        const int cnt = *pcnt;
        float* xv = (float*)(smem + SM_XV) + w * 64;
        for (int f = w; f < cnt; f += 8) {
            int r = lst[f];
            const float* xp = in + (size_t)b * DDIM * HWSZ +
                              ((base + r) & (HWSZ - 1));
            xv[lane]      = xp[(size_t)lane * HWSZ];
            xv[lane + 32] = xp[(size_t)(lane + 32) * HWSZ];
            __syncwarp();
            float bd = FLT_MAX; int bi = 0;
            for (int kc = 0; kc < 32; kc++) {
                int k = kc * 32 + lane;
                const float* ep = emb + (size_t)k * DDIM;
                float lo = 0.f, hi = 0.f;
#pragma unroll
                for (int d = 0; d < DDIM / 2; d++) {
                    lo = __fmaf_rn(xv[2 * d],     __ldg(&ep[2 * d]),     lo);
                    hi = __fmaf_rn(xv[2 * d + 1], __ldg(&ep[2 * d + 1]), hi);
                }
                float dot  = lo + hi;
                float dist = esq_s[k] - 2.0f * dot;
                if (dist < bd) { bd = dist; bi = k; }
            }
#pragma unroll
            for (int off = 16; off > 0; off >>= 1) {
                float od = __shfl_xor_sync(0xffffffffu, bd, off);
                int   oi = __shfl_xor_sync(0xffffffffu, bi, off);
                if (od < bd || (od == bd && oi < bi)) { bd = od; bi = oi; }
            }
            if (lane == 0) fidx[r] = bi;
            __syncwarp();
        }
    }
    __syncthreads();

    // ---- outputs ----
    if (t < 128) {
        int bidx = fidx[t];
        out[base + t] = (float)bidx;
        atomicAdd(&g_counts[bidx], 1);
    }
    {   // quantized scatter: 2 threads per point, 32 channels each
        int p    = t & 127;
        int half = t >> 7;
        int bidx = fidx[p];
        const float* er = emb + (size_t)bidx * DDIM + half * 32;
        float* oq = out + QOFF + (size_t)b * DDIM * HWSZ +
                    ((base + p) & (HWSZ - 1)) + (size_t)half * 32 * HWSZ;
#pragma unroll
        for (int i = 0; i < 32; i++)
            oq[(size_t)i * HWSZ] = __ldg(&er[i]);
    }
}

// ---------------------------------------------------------------------------
// Perplexity
// ---------------------------------------------------------------------------
__global__ void vq_perp(float* __restrict__ out) {
    __shared__ float red[32];
    int k = threadIdx.x;
    float p = (float)g_counts[k] * (1.0f / (float)NPTS);
    float v = p * logf(p + 1e-10f);
#pragma unroll
    for (int s = 16; s > 0; s >>= 1) v += __shfl_xor_sync(0xffffffffu, v, s);
    if ((k & 31) == 0) red[k >> 5] = v;
    __syncthreads();
    if (k < 32) {
        float wv = red[k];
#pragma unroll
        for (int s = 16; s > 0; s >>= 1) wv += __shfl_xor_sync(0xffffffffu, wv, s);
        if (k == 0) out[POFF] = expf(-wv);
    }
}

// ---------------------------------------------------------------------------
extern "C" void kernel_launch(void* const* d_in, const int* in_sizes, int n_in,
                              void* d_out, int out_size) {
    const float* x   = (const float*)d_in[0];   // (32, 64, 64, 64) fp32
    const float* emb = (const float*)d_in[1];   // (1024, 64) fp32
    float* out = (float*)d_out;

    cudaFuncSetAttribute(vq_main, cudaFuncAttributeMaxDynamicSharedMemorySize,
                         SM_TOTAL);

    vq_prep<<<8, 128>>>(emb);
    vq_digits<<<64, 256>>>(emb);
    vq_main<<<NPTS / 128, 256, SM_TOTAL>>>(x, emb, out);
    vq_perp<<<1, KCODES>>>(out);
}

// round 11
// speedup vs baseline: 1.2696x; 1.2696x over previous
#include <cuda_runtime.h>
#include <cuda_bf16.h>
#include <math.h>
#include <float.h>
#include <stdint.h>

// Problem constants
#define NPTS   131072          // 32 * 64 * 64 points
#define DDIM   64
#define KCODES 1024
#define HWSZ   4096
#define QOFF   ((size_t)NPTS)
#define QSZ    ((size_t)32*64*4096)
#define POFF   (QOFF + QSZ)

#define TAU    2e-3f           // MMA top-2 gap below which we rescan exactly

#define PITCH   144            // bytes per smem row -> conflict-free ldmatrix
#define ASPLIT  (128 * PITCH)  // 18432 B per split tile
#define BUFSZ   (2 * ASPLIT)   // 36864 B: one B buffer (2 splits) == A region
// smem layout (A overlaid with B buffer 0)
#define SM_ESQ   0             // 1024 f32 = 4096
#define SM_FIDX  4096
#define SM_CNT   4608
#define SM_LST   4624
#define SM_XV    5152          // 8 warps x 64 f32
#define SM_BUF0  7200          // A splits during prologue, then B buf 0
#define SM_BUF1  (SM_BUF0 + BUFSZ)
#define SM_TOTAL (SM_BUF1 + BUFSZ)   // 80928 B -> 2 CTAs/SM

// ---- scratch (no cudaMalloc) ----
__device__ int           g_counts[KCODES];
__device__ float         g_esq[KCODES];
__device__ __nv_bfloat16 g_e0[KCODES * DDIM];
__device__ __nv_bfloat16 g_e1[KCODES * DDIM];

// ---- PTX helpers (baseline ISA, sm_80-compatible) ----
__device__ __forceinline__ uint32_t smem_u32(const void* p) {
    uint32_t a;
    asm("{ .reg .u64 t; cvta.to.shared.u64 t, %1; cvt.u32.u64 %0, t; }"
        : "=r"(a) : "l"(p));
    return a;
}
#define CP_ASYNC16(dst, src) \
    asm volatile("cp.async.cg.shared.global [%0], [%1], 16;" \
                 :: "r"(dst), "l"(src) : "memory")
#define CP_COMMIT() asm volatile("cp.async.commit_group;" ::: "memory")
#define CP_WAIT1()  asm volatile("cp.async.wait_group 1;" ::: "memory")
#define CP_WAIT0()  asm volatile("cp.async.wait_group 0;" ::: "memory")

#define LDSM_X4(r, addr)                                                      \
    asm volatile("ldmatrix.sync.aligned.m8n8.x4.shared.b16 {%0,%1,%2,%3}, [%4];" \
                 : "=r"((r)[0]), "=r"((r)[1]), "=r"((r)[2]), "=r"((r)[3])     \
                 : "r"(addr))

#define MMA16816(c, a, b)                                                     \
    asm volatile("mma.sync.aligned.m16n8k16.row.col.f32.bf16.bf16.f32 "       \
                 "{%0,%1,%2,%3}, {%4,%5,%6,%7}, {%8,%9}, {%0,%1,%2,%3};"      \
                 : "+f"((c)[0]), "+f"((c)[1]), "+f"((c)[2]), "+f"((c)[3])     \
                 : "r"((a)[0]), "r"((a)[1]), "r"((a)[2]), "r"((a)[3]),        \
                   "r"((b)[0]), "r"((b)[1]))

// best + second-best distance (index only for best)
__device__ __forceinline__ void upd2(float& bd, int& bi, float& sd,
                                     float d, int idx) {
    if (d < bd)      { sd = bd; bd = d; bi = idx; }
    else if (d < sd) { sd = d; }
}
__device__ __forceinline__ void merge2(float& bd, int& bi, float& sd,
                                       float obd, int obi, float osd) {
    if (obd < bd || (obd == bd && obi < bi)) {
        sd = fminf(bd, osd); bd = obd; bi = obi;
    } else {
        sd = fminf(sd, obd);
    }
}

// ---------------------------------------------------------------------------
// esq: VERBATIM Round-1 arithmetic (matches reference decisions) + zero counts
// ---------------------------------------------------------------------------
__global__ void vq_prep(const float* __restrict__ emb) {
    int k = blockIdx.x * blockDim.x + threadIdx.x;
    if (k < KCODES) {
        const float4* row = (const float4*)(emb + (size_t)k * DDIM);
        float s = 0.f;
#pragma unroll
        for (int i = 0; i < DDIM / 4; i++) {
            float4 v = row[i];
            s += v.x * v.x + v.y * v.y + v.z * v.z + v.w * v.w;
        }
        g_esq[k]    = s;
        g_counts[k] = 0;
    }
}

// bf16 2-way splits, fully parallel: 16384 threads, 4 dims each.
__global__ void vq_split(const float* __restrict__ emb) {
    int idx = blockIdx.x * blockDim.x + threadIdx.x;   // 0..16383
    int k = idx >> 4, g = idx & 15;
    float4 v = *(const float4*)(emb + (size_t)k * DDIM + g * 4);
    __nv_bfloat16 h0x = __float2bfloat16_rn(v.x);
    __nv_bfloat16 h0y = __float2bfloat16_rn(v.y);
    __nv_bfloat16 h0z = __float2bfloat16_rn(v.z);
    __nv_bfloat16 h0w = __float2bfloat16_rn(v.w);
    __nv_bfloat16 h1x = __float2bfloat16_rn(v.x - __bfloat162float(h0x));
    __nv_bfloat16 h1y = __float2bfloat16_rn(v.y - __bfloat162float(h0y));
    __nv_bfloat16 h1z = __float2bfloat16_rn(v.z - __bfloat162float(h0z));
    __nv_bfloat16 h1w = __float2bfloat16_rn(v.w - __bfloat162float(h0w));
    __nv_bfloat162* p0 = (__nv_bfloat162*)(g_e0 + (size_t)k * DDIM + g * 4);
    __nv_bfloat162* p1 = (__nv_bfloat162*)(g_e1 + (size_t)k * DDIM + g * 4);
    p0[0] = __nv_bfloat162(h0x, h0y);  p0[1] = __nv_bfloat162(h0z, h0w);
    p1[0] = __nv_bfloat162(h1x, h1y);  p1[1] = __nv_bfloat162(h1z, h1w);
}

// ---------------------------------------------------------------------------
// Main: 256 threads (8 warps), 128 points/CTA, 1024 CTAs, 2 CTAs/SM.
// 3-product bf16 mma.sync ranking + gap-gated exact R1-arithmetic rescan.
// esq is pre-loaded into the MMA accumulators (saves per-j scalar adds).
// ---------------------------------------------------------------------------
__global__ __launch_bounds__(256, 2)
void vq_main(const float* __restrict__ in, const float* __restrict__ emb,
             float* __restrict__ out) {
    extern __shared__ char smem[];
    float* esq_s = (float*)(smem + SM_ESQ);
    int*   fidx  = (int*)(smem + SM_FIDX);
    int*   pcnt  = (int*)(smem + SM_CNT);
    int*   lst   = (int*)(smem + SM_LST);
    const uint32_t sbase = smem_u32(smem);
    const int t    = threadIdx.x;
    const int lane = t & 31;
    const int w    = t >> 5;
    const int m0   = w * 16;
    const int base = blockIdx.x * 128;
    const int b    = base >> 12;
    const int tg   = lane & 3;

    // ---- B tile loader via cp.async: 2 splits x 128 codes x 128B ----
    auto issue_B = [&](int tt, int buf) {
        uint32_t bb = sbase + (buf ? SM_BUF1 : SM_BUF0);
#pragma unroll
        for (int i = 0; i < 8; i++) {
            int c   = t + i * 256;           // 0..2047 chunk id
            int s   = c >> 10;               // split 0/1
            int r   = c & 1023;
            int row = r >> 3, ch = r & 7;
            uint32_t dst = bb + s * ASPLIT + row * PITCH + ch * 16;
            const __nv_bfloat16* srcp = (s == 0) ? g_e0 : g_e1;
            const char* src = (const char*)srcp +
                              ((size_t)(tt * 128 + row) * DDIM + ch * 8) * 2;
            CP_ASYNC16(dst, src);
        }
        CP_COMMIT();
    };

    if (t == 0) *pcnt = 0;
#pragma unroll
    for (int i = 0; i < KCODES / 256; i++)
        esq_s[t + i * 256] = g_esq[t + i * 256];

    // ---- A build into BUF0: point t, split(-2x) into 2 bf16 rows ----
    if (t < 128) {
        const float* xp = in + (size_t)b * DDIM * HWSZ + ((base + t) & (HWSZ - 1));
        uint32_t* r0 = (uint32_t*)(smem + SM_BUF0 + 0 * ASPLIT + t * PITCH);
        uint32_t* r1 = (uint32_t*)(smem + SM_BUF0 + 1 * ASPLIT + t * PITCH);
#pragma unroll
        for (int d = 0; d < DDIM; d += 2) {
            float va = -2.0f * xp[(size_t)d * HWSZ];
            float vb = -2.0f * xp[(size_t)(d + 1) * HWSZ];
            __nv_bfloat16 a0 = __float2bfloat16_rn(va);
            __nv_bfloat16 a1 = __float2bfloat16_rn(va - __bfloat162float(a0));
            __nv_bfloat16 b0 = __float2bfloat16_rn(vb);
            __nv_bfloat16 b1 = __float2bfloat16_rn(vb - __bfloat162float(b0));
            r0[d >> 1] = (uint32_t)__bfloat16_as_ushort(a0) |
                         ((uint32_t)__bfloat16_as_ushort(b0) << 16);
            r1[d >> 1] = (uint32_t)__bfloat16_as_ushort(a1) |
                         ((uint32_t)__bfloat16_as_ushort(b1) << 16);
        }
    }
    __syncthreads();

    // ---- A fragments to registers (frees BUF0 for B tiles) ----
    uint32_t af[2][4][4];
#pragma unroll
    for (int s = 0; s < 2; s++)
#pragma unroll
        for (int k = 0; k < 4; k++) {
            uint32_t addr = sbase + SM_BUF0 + s * ASPLIT +
                            (m0 + (lane & 15)) * PITCH + k * 32 + (lane >> 4) * 16;
            LDSM_X4(af[s][k], addr);
        }
    __syncthreads();                         // all LDSM done before overwrite

    issue_B(0, 0);                           // into former A region
    issue_B(1, 1);

    float bd0 = FLT_MAX, sd0 = FLT_MAX, bd1 = FLT_MAX, sd1 = FLT_MAX;
    int   bi0 = 0, bi1 = 0;

    for (int tt = 0; tt < 8; tt++) {
        if (tt < 7) { CP_WAIT1(); } else { CP_WAIT0(); }
        __syncthreads();
        const uint32_t bbase = sbase + ((tt & 1) ? SM_BUF1 : SM_BUF0);

#pragma unroll 4
        for (int j = 0; j < 16; j++) {
            uint32_t bf[2][2][4];
#pragma unroll
            for (int s = 0; s < 2; s++)
#pragma unroll
                for (int kk = 0; kk < 2; kk++) {
                    uint32_t addr = bbase + s * ASPLIT +
                                    (j * 8 + (lane & 7)) * PITCH +
                                    kk * 64 + (lane >> 3) * 16;
                    LDSM_X4(bf[s][kk], addr);
                }

            const int cb = tt * 128 + j * 8 + 2 * tg;
            const float e0 = esq_s[cb], e1 = esq_s[cb + 1];
            // esq pre-loaded into accA; accB/accC start at 0
            float accA[4] = {e0, e1, e0, e1};
            float accB[4] = {0.f, 0.f, 0.f, 0.f};
            float accC[4] = {0.f, 0.f, 0.f, 0.f};
#pragma unroll
            for (int k = 0; k < 4; k++) {
                const uint32_t* b0k = &bf[0][k >> 1][(k & 1) * 2];
                const uint32_t* b1k = &bf[1][k >> 1][(k & 1) * 2];
                MMA16816(accA, af[0][k], b0k);   // x0*e0  (+esq)
                MMA16816(accB, af[0][k], b1k);   // x0*e1
                MMA16816(accC, af[1][k], b0k);   // x1*e0
            }

            upd2(bd0, bi0, sd0, (accB[0] + accC[0]) + accA[0], cb);
            upd2(bd0, bi0, sd0, (accB[1] + accC[1]) + accA[1], cb + 1);
            upd2(bd1, bi1, sd1, (accB[2] + accC[2]) + accA[2], cb);
            upd2(bd1, bi1, sd1, (accB[3] + accC[3]) + accA[3], cb + 1);
        }

        __syncthreads();                     // everyone done reading buf
        if (tt + 2 < 8) issue_B(tt + 2, tt & 1);
    }

    // ---- merge top-2 across the 4 lanes sharing each row ----
#pragma unroll
    for (int off = 1; off <= 2; off <<= 1) {
        float obd = __shfl_xor_sync(0xffffffffu, bd0, off);
        int   obi = __shfl_xor_sync(0xffffffffu, bi0, off);
        float osd = __shfl_xor_sync(0xffffffffu, sd0, off);
        merge2(bd0, bi0, sd0, obd, obi, osd);
        obd = __shfl_xor_sync(0xffffffffu, bd1, off);
        obi = __shfl_xor_sync(0xffffffffu, bi1, off);
        osd = __shfl_xor_sync(0xffffffffu, sd1, off);
        merge2(bd1, bi1, sd1, obd, obi, osd);
    }
    if (tg == 0) {
        int g  = lane >> 2;
        int r0 = m0 + g, r1 = m0 + g + 8;
        fidx[r0] = bi0;
        fidx[r1] = bi1;
        if (sd0 - bd0 <= TAU) lst[atomicAdd(pcnt, 1)] = r0;
        if (sd1 - bd1 <= TAU) lst[atomicAdd(pcnt, 1)] = r1;
    }
    __syncthreads();

    // ---- near-tie rescan: EXACT Round-1 arithmetic, all 1024 codes ----
    {
        const int cnt = *pcnt;
        float* xv = (float*)(smem + SM_XV) + w * 64;
        for (int f = w; f < cnt; f += 8) {
            int r = lst[f];
            const float* xp = in + (size_t)b * DDIM * HWSZ +
                              ((base + r) & (HWSZ - 1));
            xv[lane]      = xp[(size_t)lane * HWSZ];
            xv[lane + 32] = xp[(size_t)(lane + 32) * HWSZ];
            __syncwarp();
            float bd = FLT_MAX; int bi = 0;
            for (int kc = 0; kc < 32; kc++) {
                int k = kc * 32 + lane;          // ascending in k per lane
                const float* ep = emb + (size_t)k * DDIM;
                float lo = 0.f, hi = 0.f;
#pragma unroll
                for (int d = 0; d < DDIM / 2; d++) {
                    lo = __fmaf_rn(xv[2 * d],     __ldg(&ep[2 * d]),     lo);
                    hi = __fmaf_rn(xv[2 * d + 1], __ldg(&ep[2 * d + 1]), hi);
                }
                float dot  = lo + hi;
                float dist = esq_s[k] - 2.0f * dot;
                if (dist < bd) { bd = dist; bi = k; }
            }
#pragma unroll
            for (int off = 16; off > 0; off >>= 1) {
                float od = __shfl_xor_sync(0xffffffffu, bd, off);
                int   oi = __shfl_xor_sync(0xffffffffu, bi, off);
                if (od < bd || (od == bd && oi < bi)) { bd = od; bi = oi; }
            }
            if (lane == 0) fidx[r] = bi;
            __syncwarp();
        }
    }
    __syncthreads();

    // ---- outputs ----
    if (t < 128) {
        int bidx = fidx[t];
        out[base + t] = (float)bidx;
        atomicAdd(&g_counts[bidx], 1);
    }
    {   // quantized scatter: 2 threads per point, 32 channels each
        int p    = t & 127;
        int half = t >> 7;
        int bidx = fidx[p];
        const float* er = emb + (size_t)bidx * DDIM + half * 32;
        float* oq = out + QOFF + (size_t)b * DDIM * HWSZ +
                    ((base + p) & (HWSZ - 1)) + (size_t)half * 32 * HWSZ;
#pragma unroll
        for (int i = 0; i < 32; i++)
            oq[(size_t)i * HWSZ] = __ldg(&er[i]);
    }
}

// ---------------------------------------------------------------------------
// Perplexity
// ---------------------------------------------------------------------------
__global__ void vq_perp(float* __restrict__ out) {
    __shared__ float red[32];
    int k = threadIdx.x;
    float p = (float)g_counts[k] * (1.0f / (float)NPTS);
    float v = p * logf(p + 1e-10f);
#pragma unroll
    for (int s = 16; s > 0; s >>= 1) v += __shfl_xor_sync(0xffffffffu, v, s);
    if ((k & 31) == 0) red[k >> 5] = v;
    __syncthreads();
    if (k < 32) {
        float wv = red[k];
#pragma unroll
        for (int s = 16; s > 0; s >>= 1) wv += __shfl_xor_sync(0xffffffffu, wv, s);
        if (k == 0) out[POFF] = expf(-wv);
    }
}

// ---------------------------------------------------------------------------
extern "C" void kernel_launch(void* const* d_in, const int* in_sizes, int n_in,
                              void* d_out, int out_size) {
    const float* x   = (const float*)d_in[0];   // (32, 64, 64, 64) fp32
    const float* emb = (const float*)d_in[1];   // (1024, 64) fp32
    float* out = (float*)d_out;

    cudaFuncSetAttribute(vq_main, cudaFuncAttributeMaxDynamicSharedMemorySize,
                         SM_TOTAL);

    vq_prep<<<8, 128>>>(emb);
    vq_split<<<64, 256>>>(emb);
    vq_main<<<NPTS / 128, 256, SM_TOTAL>>>(x, emb, out);
    vq_perp<<<1, KCODES>>>(out);
}

// round 12
// speedup vs baseline: 1.4502x; 1.1422x over previous
#include <cuda_runtime.h>
#include <cuda_bf16.h>
#include <math.h>
#include <float.h>
#include <stdint.h>

// Problem constants
#define NPTS   131072          // 32 * 64 * 64 points
#define DDIM   64
#define KCODES 1024
#define HWSZ   4096
#define QOFF   ((size_t)NPTS)
#define QSZ    ((size_t)32*64*4096)
#define POFF   (QOFF + QSZ)

#define MARGIN 0.35f           // coarse-window margin (~9.5 sigma of bf16 noise)
#define CAP    32              // candidate capacity per point
#define XSP    65              // xs row stride (floats) -> conflict-free LDS

#define PITCH   144            // bytes per smem row -> conflict-free ldmatrix
#define ASPLIT  (128 * PITCH)  // 18432 B: one tile (128 rows x 64 bf16)
// smem layout
#define SM_ESQ   0             // 1024 f32 = 4096
#define SM_FIDX  4096          // 128 int
#define SM_CNT2  4608          // 128 int candidate counts
#define SM_PCNT  5120          // overflow counter
#define SM_LST   5136          // 128 int overflow rows
#define SM_PD    5648          // 256 f32 partial dists
#define SM_PI    6672          // 256 int partial idx
#define SM_CAND  7696          // 128 * CAP ints = 16384
#define SM_BUF0  24080         // B buf 0 (A tile during prologue); xs after loop
#define SM_BUF1  (SM_BUF0 + ASPLIT)
#define SM_TOTAL (SM_BUF1 + ASPLIT)   // 60944 B -> 2 CTAs/SM

// ---- scratch (no cudaMalloc) ----
__device__ int           g_counts[KCODES];
__device__ float         g_esq[KCODES];
__device__ __nv_bfloat16 g_e0[KCODES * DDIM];

// ---- PTX helpers (baseline ISA, sm_80-compatible) ----
__device__ __forceinline__ uint32_t smem_u32(const void* p) {
    uint32_t a;
    asm("{ .reg .u64 t; cvta.to.shared.u64 t, %1; cvt.u32.u64 %0, t; }"
        : "=r"(a) : "l"(p));
    return a;
}
#define CP_ASYNC16(dst, src) \
    asm volatile("cp.async.cg.shared.global [%0], [%1], 16;" \
                 :: "r"(dst), "l"(src) : "memory")
#define CP_COMMIT() asm volatile("cp.async.commit_group;" ::: "memory")
#define CP_WAIT1()  asm volatile("cp.async.wait_group 1;" ::: "memory")
#define CP_WAIT0()  asm volatile("cp.async.wait_group 0;" ::: "memory")

#define LDSM_X4(r, addr)                                                      \
    asm volatile("ldmatrix.sync.aligned.m8n8.x4.shared.b16 {%0,%1,%2,%3}, [%4];" \
                 : "=r"((r)[0]), "=r"((r)[1]), "=r"((r)[2]), "=r"((r)[3])     \
                 : "r"(addr))

#define MMA16816(c, a, b)                                                     \
    asm volatile("mma.sync.aligned.m16n8k16.row.col.f32.bf16.bf16.f32 "       \
                 "{%0,%1,%2,%3}, {%4,%5,%6,%7}, {%8,%9}, {%0,%1,%2,%3};"      \
                 : "+f"((c)[0]), "+f"((c)[1]), "+f"((c)[2]), "+f"((c)[3])     \
                 : "r"((a)[0]), "r"((a)[1]), "r"((a)[2]), "r"((a)[3]),        \
                   "r"((b)[0]), "r"((b)[1]))

// ---------------------------------------------------------------------------
// esq: VERBATIM Round-1 arithmetic (matches reference decisions) + zero counts
// ---------------------------------------------------------------------------
__global__ void vq_prep(const float* __restrict__ emb) {
    int k = blockIdx.x * blockDim.x + threadIdx.x;
    if (k < KCODES) {
        const float4* row = (const float4*)(emb + (size_t)k * DDIM);
        float s = 0.f;
#pragma unroll
        for (int i = 0; i < DDIM / 4; i++) {
            float4 v = row[i];
            s += v.x * v.x + v.y * v.y + v.z * v.z + v.w * v.w;
        }
        g_esq[k]    = s;
        g_counts[k] = 0;
    }
}

// bf16 leading digits only, fully parallel: 16384 threads, 4 dims each.
__global__ void vq_split(const float* __restrict__ emb) {
    int idx = blockIdx.x * blockDim.x + threadIdx.x;   // 0..16383
    int k = idx >> 4, g = idx & 15;
    float4 v = *(const float4*)(emb + (size_t)k * DDIM + g * 4);
    __nv_bfloat162* p0 = (__nv_bfloat162*)(g_e0 + (size_t)k * DDIM + g * 4);
    p0[0] = __nv_bfloat162(__float2bfloat16_rn(v.x), __float2bfloat16_rn(v.y));
    p0[1] = __nv_bfloat162(__float2bfloat16_rn(v.z), __float2bfloat16_rn(v.w));
}

// ---------------------------------------------------------------------------
// Main: 256 threads (8 warps), 128 points/CTA, 1024 CTAs, 2 CTAs/SM.
// Coarse 1-product bf16 MMA -> candidate set -> exact R1-fp32 verification.
// ---------------------------------------------------------------------------
__global__ __launch_bounds__(256, 2)
void vq_main(const float* __restrict__ in, const float* __restrict__ emb,
             float* __restrict__ out) {
    extern __shared__ char smem[];
    float* esq_s = (float*)(smem + SM_ESQ);
    int*   fidx  = (int*)(smem + SM_FIDX);
    int*   cnt2  = (int*)(smem + SM_CNT2);
    int*   pcnt  = (int*)(smem + SM_PCNT);
    int*   lst   = (int*)(smem + SM_LST);
    float* pd    = (float*)(smem + SM_PD);
    int*   pi    = (int*)(smem + SM_PI);
    int*   cand  = (int*)(smem + SM_CAND);
    float* xs    = (float*)(smem + SM_BUF0);   // after mainloop only
    const uint32_t sbase = smem_u32(smem);
    const int t    = threadIdx.x;
    const int lane = t & 31;
    const int w    = t >> 5;
    const int m0   = w * 16;
    const int base = blockIdx.x * 128;
    const int b    = base >> 12;
    const int tg   = lane & 3;
    const int g    = lane >> 2;
    const int row0 = m0 + g;
    const int row1 = m0 + g + 8;

    // ---- B loader via cp.async: 128 codes x 128B = 1024 x 16B chunks ----
    auto issue_B = [&](int tt, int buf) {
        uint32_t bb = sbase + (buf ? SM_BUF1 : SM_BUF0);
#pragma unroll
        for (int i = 0; i < 4; i++) {
            int c   = t + i * 256;           // 0..1023
            int row = c >> 3, ch = c & 7;
            uint32_t dst = bb + row * PITCH + ch * 16;
            const char* src = (const char*)g_e0 +
                              ((size_t)(tt * 128 + row) * DDIM + ch * 8) * 2;
            CP_ASYNC16(dst, src);
        }
        CP_COMMIT();
    };

    if (t == 0) *pcnt = 0;
    if (t < 128) cnt2[t] = 0;
#pragma unroll
    for (int i = 0; i < KCODES / 256; i++)
        esq_s[t + i * 256] = g_esq[t + i * 256];

    // ---- A build into BUF0: point t, bf16(-2x) single digit ----
    if (t < 128) {
        const float* xp = in + (size_t)b * DDIM * HWSZ + ((base + t) & (HWSZ - 1));
        uint32_t* r0 = (uint32_t*)(smem + SM_BUF0 + t * PITCH);
#pragma unroll
        for (int d = 0; d < DDIM; d += 2) {
            float va = -2.0f * xp[(size_t)d * HWSZ];
            float vb = -2.0f * xp[(size_t)(d + 1) * HWSZ];
            __nv_bfloat16 a0 = __float2bfloat16_rn(va);
            __nv_bfloat16 b0 = __float2bfloat16_rn(vb);
            r0[d >> 1] = (uint32_t)__bfloat16_as_ushort(a0) |
                         ((uint32_t)__bfloat16_as_ushort(b0) << 16);
        }
    }
    __syncthreads();

    // ---- A fragments to registers (frees BUF0 for B tiles) ----
    uint32_t af[4][4];
#pragma unroll
    for (int k = 0; k < 4; k++) {
        uint32_t addr = sbase + SM_BUF0 + (m0 + (lane & 15)) * PITCH +
                        k * 32 + (lane >> 4) * 16;
        LDSM_X4(af[k], addr);
    }
    __syncthreads();                         // all LDSM done before overwrite

    issue_B(0, 0);
    issue_B(1, 1);

    float rb0 = FLT_MAX, rb1 = FLT_MAX;      // coarse running bests per row

    for (int tt = 0; tt < 8; tt++) {
        if (tt < 7) { CP_WAIT1(); } else { CP_WAIT0(); }
        __syncthreads();
        const uint32_t bbase = sbase + ((tt & 1) ? SM_BUF1 : SM_BUF0);

#pragma unroll 4
        for (int j = 0; j < 16; j++) {
            uint32_t bf[2][4];
#pragma unroll
            for (int kk = 0; kk < 2; kk++) {
                uint32_t addr = bbase + (j * 8 + (lane & 7)) * PITCH +
                                kk * 64 + (lane >> 3) * 16;
                LDSM_X4(bf[kk], addr);
            }

            const int cb = tt * 128 + j * 8 + 2 * tg;
            const float e0 = esq_s[cb], e1 = esq_s[cb + 1];
            float accA[4] = {e0, e1, e0, e1};
#pragma unroll
            for (int k = 0; k < 4; k++)
                MMA16816(accA, af[k], &bf[k >> 1][(k & 1) * 2]);

            // candidate collection (coarse window)
#pragma unroll
            for (int p = 0; p < 4; p++) {
                float d  = accA[p];
                float rb = (p < 2) ? rb0 : rb1;
                if (d <= rb + MARGIN) {
                    int row  = (p < 2) ? row0 : row1;
                    int slot = atomicAdd(&cnt2[row], 1);
                    if (slot < CAP) cand[row * CAP + slot] = cb + (p & 1);
                    if (d < rb) { if (p < 2) rb0 = d; else rb1 = d; }
                }
            }
            // merge running bests across the 4 lanes sharing each row
            rb0 = fminf(rb0, __shfl_xor_sync(0xffffffffu, rb0, 1));
            rb0 = fminf(rb0, __shfl_xor_sync(0xffffffffu, rb0, 2));
            rb1 = fminf(rb1, __shfl_xor_sync(0xffffffffu, rb1, 1));
            rb1 = fminf(rb1, __shfl_xor_sync(0xffffffffu, rb1, 2));
        }

        __syncthreads();                     // everyone done reading buf
        if (tt + 2 < 8) issue_B(tt + 2, tt & 1);
    }

    // ---- stage x into smem (BUF region is free now), conflict-free pad ----
    {
        int p = t & 127, half = t >> 7;
        const float* xp = in + (size_t)b * DDIM * HWSZ + ((base + p) & (HWSZ - 1));
#pragma unroll
        for (int i = 0; i < 32; i++)
            xs[p * XSP + half * 32 + i] = xp[(size_t)(half * 32 + i) * HWSZ];
    }
    if (t < 128 && cnt2[t] > CAP) lst[atomicAdd(pcnt, 1)] = t;
    __syncthreads();

    // ---- exact R1-fp32 evaluation of candidates (2 threads per point) ----
    {
        int p = t & 127, half = t >> 7;
        int mn = min(cnt2[p], CAP);
        const float* xv = xs + p * XSP;
        float bd = FLT_MAX; int bi = 0x7fffffff;
        for (int c = half; c < mn; c += 2) {
            int k = cand[p * CAP + c];
            const float4* ep = (const float4*)(emb + (size_t)k * DDIM);
            float lo = 0.f, hi = 0.f;
#pragma unroll
            for (int q = 0; q < DDIM / 4; q++) {
                float4 ev = __ldg(&ep[q]);
                lo = __fmaf_rn(xv[4 * q],     ev.x, lo);
                hi = __fmaf_rn(xv[4 * q + 1], ev.y, hi);
                lo = __fmaf_rn(xv[4 * q + 2], ev.z, lo);
                hi = __fmaf_rn(xv[4 * q + 3], ev.w, hi);
            }
            float dist = esq_s[k] - 2.0f * (lo + hi);
            if (dist < bd || (dist == bd && k < bi)) { bd = dist; bi = k; }
        }
        pd[t] = bd; pi[t] = bi;
    }
    __syncthreads();
    if (t < 128) {
        float bd = pd[t]; int bi = pi[t];
        float od = pd[t + 128]; int oi = pi[t + 128];
        if (od < bd || (od == bd && oi < bi)) { bd = od; bi = oi; }
        fidx[t] = bi;
    }
    __syncthreads();

    // ---- overflow full rescan: one warp per flagged point, exact R1 ----
    {
        const int cnt = *pcnt;
        for (int f = w; f < cnt; f += 8) {
            int r = lst[f];
            const float* xv = xs + r * XSP;
            float bd = FLT_MAX; int bi = 0;
            for (int kc = 0; kc < 32; kc++) {
                int k = kc * 32 + lane;
                const float* ep = emb + (size_t)k * DDIM;
                float lo = 0.f, hi = 0.f;
#pragma unroll
                for (int d = 0; d < DDIM / 2; d++) {
                    lo = __fmaf_rn(xv[2 * d],     __ldg(&ep[2 * d]),     lo);
                    hi = __fmaf_rn(xv[2 * d + 1], __ldg(&ep[2 * d + 1]), hi);
                }
                float dist = esq_s[k] - 2.0f * (lo + hi);
                if (dist < bd) { bd = dist; bi = k; }
            }
#pragma unroll
            for (int off = 16; off > 0; off >>= 1) {
                float od = __shfl_xor_sync(0xffffffffu, bd, off);
                int   oi = __shfl_xor_sync(0xffffffffu, bi, off);
                if (od < bd || (od == bd && oi < bi)) { bd = od; bi = oi; }
            }
            if (lane == 0) fidx[r] = bi;
            __syncwarp();
        }
    }
    __syncthreads();

    // ---- outputs ----
    if (t < 128) {
        int bidx = fidx[t];
        out[base + t] = (float)bidx;
        atomicAdd(&g_counts[bidx], 1);
    }
    {   // quantized scatter: 2 threads per point, 32 channels each
        int p    = t & 127;
        int half = t >> 7;
        int bidx = fidx[p];
        const float* er = emb + (size_t)bidx * DDIM + half * 32;
        float* oq = out + QOFF + (size_t)b * DDIM * HWSZ +
                    ((base + p) & (HWSZ - 1)) + (size_t)half * 32 * HWSZ;
#pragma unroll
        for (int i = 0; i < 32; i++)
            oq[(size_t)i * HWSZ] = __ldg(&er[i]);
    }
}

// ---------------------------------------------------------------------------
// Perplexity
// ---------------------------------------------------------------------------
__global__ void vq_perp(float* __restrict__ out) {
    __shared__ float red[32];
    int k = threadIdx.x;
    float p = (float)g_counts[k] * (1.0f / (float)NPTS);
    float v = p * logf(p + 1e-10f);
#pragma unroll
    for (int s = 16; s > 0; s >>= 1) v += __shfl_xor_sync(0xffffffffu, v, s);
    if ((k & 31) == 0) red[k >> 5] = v;
    __syncthreads();
    if (k < 32) {
        float wv = red[k];
#pragma unroll
        for (int s = 16; s > 0; s >>= 1) wv += __shfl_xor_sync(0xffffffffu, wv, s);
        if (k == 0) out[POFF] = expf(-wv);
    }
}

// ---------------------------------------------------------------------------
extern "C" void kernel_launch(void* const* d_in, const int* in_sizes, int n_in,
                              void* d_out, int out_size) {
    const float* x   = (const float*)d_in[0];   // (32, 64, 64, 64) fp32
    const float* emb = (const float*)d_in[1];   // (1024, 64) fp32
    float* out = (float*)d_out;

    cudaFuncSetAttribute(vq_main, cudaFuncAttributeMaxDynamicSharedMemorySize,
                         SM_TOTAL);

    vq_prep<<<8, 128>>>(emb);
    vq_split<<<64, 256>>>(emb);
    vq_main<<<NPTS / 128, 256, SM_TOTAL>>>(x, emb, out);
    vq_perp<<<1, KCODES>>>(out);
}